// round 1
// baseline (speedup 1.0000x reference)
#include <cuda_runtime.h>
#include <math.h>

// Problem constants
#define BB   4          // batch
#define NN   8          // heads
#define CC   48         // channels per head
#define DIM  384        // NN*CC
#define QKV_CH 1152     // 3*DIM
#define HH   128
#define WW   128
#define HW   16384      // HH*WW
#define DVEC (CC*HW)    // 786432 per-head flattened vector length
#define SPLITS 256      // reduction splits per batch

// Scratch (device globals: no allocation allowed)
static __device__ float g_tmp[(size_t)BB * QKV_CH * HW];   // conv1x1 output
static __device__ float g_qkv[(size_t)BB * QKV_CH * HW];   // after dwconv
static __device__ float g_part[(size_t)BB * SPLITS * 80];  // reduction partials
static __device__ float g_weff[(size_t)BB * DIM * DIM];    // folded attn*proj weights

// ---------------------------------------------------------------------------
// K1: qkv conv1x1 as GEMM.  C[b][co][p] = sum_ci W[co][ci] * X[b][ci][p] + bias[co]
// Tiles: 128x128x16, 256 threads, 8x8 microtile.
// ---------------------------------------------------------------------------
__global__ __launch_bounds__(256) void k1_qkv_gemm(
    const float* __restrict__ X,      // [BB][DIM][HW]
    const float* __restrict__ Wq,     // [QKV_CH][DIM]
    const float* __restrict__ bias,   // [QKV_CH]
    float* __restrict__ Cout)         // g_tmp
{
    const int b    = blockIdx.z;
    const int row0 = blockIdx.y * 128;
    const int col0 = blockIdx.x * 128;
    const float* Xb = X + (size_t)b * DIM * HW;
    float* Cb = Cout + (size_t)b * QKV_CH * HW;

    __shared__ float As[16][128];
    __shared__ float Bs[16][128];

    const int tid = threadIdx.x;
    const int tx = tid & 15, ty = tid >> 4;

    float acc[8][8];
    #pragma unroll
    for (int i = 0; i < 8; i++)
        #pragma unroll
        for (int j = 0; j < 8; j++) acc[i][j] = 0.f;

    for (int k0 = 0; k0 < DIM; k0 += 16) {
        // load W tile 128x16 (transposed into As[k][row])
        #pragma unroll
        for (int l = 0; l < 2; l++) {
            int f = tid + l * 256;
            int r = f >> 2;
            int c4 = (f & 3) * 4;
            float4 v = *(const float4*)(Wq + (size_t)(row0 + r) * DIM + k0 + c4);
            As[c4 + 0][r] = v.x; As[c4 + 1][r] = v.y;
            As[c4 + 2][r] = v.z; As[c4 + 3][r] = v.w;
        }
        // load X tile 16x128
        #pragma unroll
        for (int l = 0; l < 2; l++) {
            int f = tid + l * 256;
            int r = f >> 5;
            int c4 = (f & 31) * 4;
            *(float4*)(&Bs[r][c4]) =
                *(const float4*)(Xb + (size_t)(k0 + r) * HW + col0 + c4);
        }
        __syncthreads();
        #pragma unroll
        for (int kk = 0; kk < 16; kk++) {
            float a[8], bv[8];
            *(float4*)(a)      = *(const float4*)(&As[kk][ty * 8]);
            *(float4*)(a + 4)  = *(const float4*)(&As[kk][ty * 8 + 4]);
            *(float4*)(bv)     = *(const float4*)(&Bs[kk][tx * 8]);
            *(float4*)(bv + 4) = *(const float4*)(&Bs[kk][tx * 8 + 4]);
            #pragma unroll
            for (int i = 0; i < 8; i++)
                #pragma unroll
                for (int j = 0; j < 8; j++)
                    acc[i][j] += a[i] * bv[j];
        }
        __syncthreads();
    }

    #pragma unroll
    for (int i = 0; i < 8; i++) {
        int r = row0 + ty * 8 + i;
        float bi = bias[r];
        float4 v0 = make_float4(acc[i][0] + bi, acc[i][1] + bi, acc[i][2] + bi, acc[i][3] + bi);
        float4 v1 = make_float4(acc[i][4] + bi, acc[i][5] + bi, acc[i][6] + bi, acc[i][7] + bi);
        float* dst = Cb + (size_t)r * HW + col0 + tx * 8;
        *(float4*)(dst)     = v0;
        *(float4*)(dst + 4) = v1;
    }
}

// ---------------------------------------------------------------------------
// K2: depthwise 3x3 conv, zero padding. g_qkv = dw(g_tmp) + b_dw
// ---------------------------------------------------------------------------
__global__ __launch_bounds__(256) void k2_dwconv(
    const float* __restrict__ w_dw,   // [QKV_CH][9]
    const float* __restrict__ b_dw)   // [QKV_CH]
{
    const int ch = blockIdx.y;
    const int b  = blockIdx.z;
    const int p  = blockIdx.x * blockDim.x + threadIdx.x;  // 0..HW-1
    const int y  = p >> 7;
    const int xp = p & 127;
    const float* src = g_tmp + ((size_t)b * QKV_CH + ch) * HW;

    float wv[9];
    #pragma unroll
    for (int i = 0; i < 9; i++) wv[i] = w_dw[ch * 9 + i];

    float s = b_dw[ch];
    #pragma unroll
    for (int dy = -1; dy <= 1; dy++) {
        int yy = y + dy;
        if (yy < 0 || yy > 127) continue;
        #pragma unroll
        for (int dx = -1; dx <= 1; dx++) {
            int xx = xp + dx;
            if (xx < 0 || xx > 127) continue;
            s += wv[(dy + 1) * 3 + (dx + 1)] * src[yy * 128 + xx];
        }
    }
    g_qkv[((size_t)b * QKV_CH + ch) * HW + p] = s;
}

// ---------------------------------------------------------------------------
// K3: partial reductions.  Per (b, split) block: 64 q.k dots + 8 |q|^2 + 8 |k|^2
// Deterministic: each block writes its own partial slot.
// ---------------------------------------------------------------------------
__device__ __forceinline__ float warp_red(float v) {
    v += __shfl_down_sync(0xffffffffu, v, 16);
    v += __shfl_down_sync(0xffffffffu, v, 8);
    v += __shfl_down_sync(0xffffffffu, v, 4);
    v += __shfl_down_sync(0xffffffffu, v, 2);
    v += __shfl_down_sync(0xffffffffu, v, 1);
    return v;
}

__global__ __launch_bounds__(256) void k3_reduce()
{
    const int b = blockIdx.y;
    const float* Q = g_qkv + (size_t)b * QKV_CH * HW;
    const float* K = Q + (size_t)DIM * HW;

    float acc[8][8], aq[8], ak[8];
    #pragma unroll
    for (int n = 0; n < 8; n++) {
        aq[n] = 0.f; ak[n] = 0.f;
        #pragma unroll
        for (int m = 0; m < 8; m++) acc[n][m] = 0.f;
    }

    const int start  = blockIdx.x * blockDim.x + threadIdx.x;
    const int stride = SPLITS * 256;
    for (int i = start; i < DVEC; i += stride) {
        float qv[8], kv[8];
        #pragma unroll
        for (int n = 0; n < 8; n++) {
            qv[n] = Q[(size_t)n * DVEC + i];
            kv[n] = K[(size_t)n * DVEC + i];
        }
        #pragma unroll
        for (int n = 0; n < 8; n++) {
            aq[n] += qv[n] * qv[n];
            ak[n] += kv[n] * kv[n];
            #pragma unroll
            for (int m = 0; m < 8; m++) acc[n][m] += qv[n] * kv[m];
        }
    }

    __shared__ float red[8][80];
    const int lane = threadIdx.x & 31, wid = threadIdx.x >> 5;
    #pragma unroll
    for (int n = 0; n < 8; n++) {
        #pragma unroll
        for (int m = 0; m < 8; m++) {
            float s = warp_red(acc[n][m]);
            if (lane == 0) red[wid][n * 8 + m] = s;
        }
        float s1 = warp_red(aq[n]); if (lane == 0) red[wid][64 + n] = s1;
        float s2 = warp_red(ak[n]); if (lane == 0) red[wid][72 + n] = s2;
    }
    __syncthreads();
    if (threadIdx.x < 80) {
        float t = 0.f;
        #pragma unroll
        for (int w = 0; w < 8; w++) t += red[w][threadIdx.x];
        g_part[((size_t)b * SPLITS + blockIdx.x) * 80 + threadIdx.x] = t;
    }
}

// ---------------------------------------------------------------------------
// K4: finalize reductions, softmax attn, fold into W_eff[b] = attn-combined proj.
// W_eff[b][co][m*48+cc] = sum_n attn[b,n,m] * w_proj[co][n*48+cc]
// One block per batch.
// ---------------------------------------------------------------------------
__global__ __launch_bounds__(256) void k4_attn_weff(
    const float* __restrict__ w_proj,     // [DIM][DIM]
    const float* __restrict__ temperature) // [1]
{
    const int b = blockIdx.x;
    __shared__ float red[80];
    __shared__ float attn[64];

    if (threadIdx.x < 80) {
        float t = 0.f;
        for (int s = 0; s < SPLITS; s++)
            t += g_part[((size_t)b * SPLITS + s) * 80 + threadIdx.x];
        red[threadIdx.x] = t;
    }
    __syncthreads();

    if (threadIdx.x < 8) {
        const int n = threadIdx.x;
        const float temp = temperature[0];
        float qn = fmaxf(sqrtf(red[64 + n]), 1e-12f);
        float logit[8];
        float mx = -1e30f;
        #pragma unroll
        for (int m = 0; m < 8; m++) {
            float kn = fmaxf(sqrtf(red[72 + m]), 1e-12f);
            float l = temp * red[n * 8 + m] / (qn * kn);
            logit[m] = l;
            mx = fmaxf(mx, l);
        }
        float sum = 0.f;
        #pragma unroll
        for (int m = 0; m < 8; m++) {
            float e = expf(logit[m] - mx);
            sum += e;
            attn[n * 8 + m] = e;
        }
        float inv = 1.f / sum;
        #pragma unroll
        for (int m = 0; m < 8; m++) attn[n * 8 + m] *= inv;
    }
    __syncthreads();

    float* Weff = g_weff + (size_t)b * DIM * DIM;
    for (int idx = threadIdx.x; idx < DIM * DIM; idx += blockDim.x) {
        const int co = idx / DIM;
        const int j  = idx % DIM;
        const int m  = j / CC;
        const int cc = j % CC;
        float s = 0.f;
        #pragma unroll
        for (int n = 0; n < 8; n++)
            s += attn[n * 8 + m] * w_proj[co * DIM + n * CC + cc];
        Weff[idx] = s;
    }
}

// ---------------------------------------------------------------------------
// K5: out[b][co][p] = sum_j W_eff[b][co][j] * V[b][j][p] + b_proj[co] + x[b][co][p]
// Same GEMM structure as K1, M=384, with residual.
// ---------------------------------------------------------------------------
__global__ __launch_bounds__(256) void k5_proj(
    const float* __restrict__ x,       // [BB][DIM][HW]
    const float* __restrict__ bias,    // [DIM]
    float* __restrict__ out)           // [BB][DIM][HW]
{
    const int b    = blockIdx.z;
    const int row0 = blockIdx.y * 128;
    const int col0 = blockIdx.x * 128;
    const float* Vb = g_qkv + (size_t)b * QKV_CH * HW + (size_t)2 * DIM * HW;
    const float* Wp = g_weff + (size_t)b * DIM * DIM;
    const float* xb = x + (size_t)b * DIM * HW;
    float* ob = out + (size_t)b * DIM * HW;

    __shared__ float As[16][128];
    __shared__ float Bs[16][128];

    const int tid = threadIdx.x;
    const int tx = tid & 15, ty = tid >> 4;

    float acc[8][8];
    #pragma unroll
    for (int i = 0; i < 8; i++)
        #pragma unroll
        for (int j = 0; j < 8; j++) acc[i][j] = 0.f;

    for (int k0 = 0; k0 < DIM; k0 += 16) {
        #pragma unroll
        for (int l = 0; l < 2; l++) {
            int f = tid + l * 256;
            int r = f >> 2;
            int c4 = (f & 3) * 4;
            float4 v = *(const float4*)(Wp + (size_t)(row0 + r) * DIM + k0 + c4);
            As[c4 + 0][r] = v.x; As[c4 + 1][r] = v.y;
            As[c4 + 2][r] = v.z; As[c4 + 3][r] = v.w;
        }
        #pragma unroll
        for (int l = 0; l < 2; l++) {
            int f = tid + l * 256;
            int r = f >> 5;
            int c4 = (f & 31) * 4;
            *(float4*)(&Bs[r][c4]) =
                *(const float4*)(Vb + (size_t)(k0 + r) * HW + col0 + c4);
        }
        __syncthreads();
        #pragma unroll
        for (int kk = 0; kk < 16; kk++) {
            float a[8], bv[8];
            *(float4*)(a)      = *(const float4*)(&As[kk][ty * 8]);
            *(float4*)(a + 4)  = *(const float4*)(&As[kk][ty * 8 + 4]);
            *(float4*)(bv)     = *(const float4*)(&Bs[kk][tx * 8]);
            *(float4*)(bv + 4) = *(const float4*)(&Bs[kk][tx * 8 + 4]);
            #pragma unroll
            for (int i = 0; i < 8; i++)
                #pragma unroll
                for (int j = 0; j < 8; j++)
                    acc[i][j] += a[i] * bv[j];
        }
        __syncthreads();
    }

    #pragma unroll
    for (int i = 0; i < 8; i++) {
        int r = row0 + ty * 8 + i;
        float bi = bias[r];
        const float* xr = xb + (size_t)r * HW + col0 + tx * 8;
        float4 x0 = *(const float4*)(xr);
        float4 x1 = *(const float4*)(xr + 4);
        float4 v0 = make_float4(acc[i][0] + bi + x0.x, acc[i][1] + bi + x0.y,
                                acc[i][2] + bi + x0.z, acc[i][3] + bi + x0.w);
        float4 v1 = make_float4(acc[i][4] + bi + x1.x, acc[i][5] + bi + x1.y,
                                acc[i][6] + bi + x1.z, acc[i][7] + bi + x1.w);
        float* dst = ob + (size_t)r * HW + col0 + tx * 8;
        *(float4*)(dst)     = v0;
        *(float4*)(dst + 4) = v1;
    }
}

// ---------------------------------------------------------------------------
extern "C" void kernel_launch(void* const* d_in, const int* in_sizes, int n_in,
                              void* d_out, int out_size)
{
    const float* x      = (const float*)d_in[0];  // (4,8,48,128,128)
    const float* temp   = (const float*)d_in[1];  // (1,)
    const float* w_qkv  = (const float*)d_in[2];  // (1152,384,1,1)
    const float* b_qkv  = (const float*)d_in[3];  // (1152,)
    const float* w_dw   = (const float*)d_in[4];  // (1152,1,3,3)
    const float* b_dw   = (const float*)d_in[5];  // (1152,)
    const float* w_proj = (const float*)d_in[6];  // (384,384,1,1)
    const float* b_proj = (const float*)d_in[7];  // (384,)
    float* out = (float*)d_out;

    float* tmp_ptr;
    cudaGetSymbolAddress((void**)&tmp_ptr, g_tmp);

    // K1: conv1x1 qkv (GEMM 1152x384 @ 384x16384, per batch)
    {
        dim3 grid(HW / 128, QKV_CH / 128, BB);
        k1_qkv_gemm<<<grid, 256>>>(x, w_qkv, b_qkv, tmp_ptr);
    }
    // K2: depthwise 3x3
    {
        dim3 grid(HW / 256, QKV_CH, BB);
        k2_dwconv<<<grid, 256>>>(w_dw, b_dw);
    }
    // K3: q.k / |q|^2 / |k|^2 partial reductions
    {
        dim3 grid(SPLITS, BB);
        k3_reduce<<<grid, 256>>>();
    }
    // K4: finalize + softmax + fold proj weights
    {
        k4_attn_weff<<<BB, 256>>>(w_proj, temp);
    }
    // K5: folded proj GEMM + bias + residual
    {
        dim3 grid(HW / 128, DIM / 128, BB);
        k5_proj<<<grid, 256>>>(x, b_proj, out);
    }
}

// round 4
// speedup vs baseline: 2.4992x; 2.4992x over previous
#include <cuda_runtime.h>
#include <cuda_bf16.h>
#include <mma.h>
#include <math.h>

#define BB 4
#define DIM 384
#define QKV_CH 1152
#define HW_ 16384
#define CC_ 48
#define DVEC 786432
#define SPLITS 256

namespace wx = nvcuda::wmma;

static __device__ float g_tmp[(size_t)BB * QKV_CH * HW_];
static __device__ float g_qk[(size_t)BB * 2 * DIM * HW_];
static __device__ __nv_bfloat16 g_vb[(size_t)BB * DIM * HW_];
static __device__ __nv_bfloat16 g_xb[(size_t)BB * DIM * HW_];
static __device__ __nv_bfloat16 g_wqb[(size_t)QKV_CH * DIM];
static __device__ float g_part[(size_t)BB * SPLITS * 80];
static __device__ float g_attn[BB * 64];
static __device__ __nv_bfloat16 g_weffb[(size_t)BB * DIM * DIM];

__global__ __launch_bounds__(256) void kc_conv_x(const float* __restrict__ src)
{
    int i = blockIdx.x * 256 + threadIdx.x;
    float4 v = ((const float4*)src)[i];
    ((__nv_bfloat162*)g_xb)[2 * i] = __floats2bfloat162_rn(v.x, v.y);
    ((__nv_bfloat162*)g_xb)[2 * i + 1] = __floats2bfloat162_rn(v.z, v.w);
}

__global__ __launch_bounds__(256) void kc_conv_w(const float* __restrict__ src)
{
    int i = blockIdx.x * 256 + threadIdx.x;
    float4 v = ((const float4*)src)[i];
    ((__nv_bfloat162*)g_wqb)[2 * i] = __floats2bfloat162_rn(v.x, v.y);
    ((__nv_bfloat162*)g_wqb)[2 * i + 1] = __floats2bfloat162_rn(v.z, v.w);
}

__device__ __forceinline__ void gemm_body(
    const __nv_bfloat16* __restrict__ Ab,
    const __nv_bfloat16* __restrict__ Bb,
    const float* __restrict__ bias,
    const float* __restrict__ rbase,
    float* __restrict__ ob)
{
    const int row0 = blockIdx.y * 128;
    const int col0 = blockIdx.x * 128;

    __shared__ __nv_bfloat16 As[128][40];
    __shared__ __nv_bfloat16 Bs[32][136];
    __shared__ float Cs[8][16][32];

    const int tid = threadIdx.x;
    const int lane = tid & 31;
    const int wid = tid >> 5;
    const int wm = wid & 1;
    const int wn = wid >> 1;

    const int ar = tid >> 2;
    const int acol = (tid & 3) * 8;
    const int br = tid >> 4;
    const int bcol = (tid & 15) * 8;

    wx::fragment<wx::accumulator, 16, 16, 16, float> c[4][2];
    for (int i = 0; i < 4; i++)
        for (int j = 0; j < 2; j++)
            wx::fill_fragment(c[i][j], 0.0f);

    uint4 ra0, ra1, rb0, rb1;

    const __nv_bfloat16* ap = Ab + (size_t)(row0 + ar) * DIM + acol;
    ra0 = *(const uint4*)(ap);
    ra1 = *(const uint4*)(ap + (size_t)64 * DIM);
    const __nv_bfloat16* bp = Bb + (size_t)br * HW_ + col0 + bcol;
    rb0 = *(const uint4*)(bp);
    rb1 = *(const uint4*)(bp + (size_t)16 * HW_);
    *(uint4*)(&As[ar][acol]) = ra0;
    *(uint4*)(&As[ar + 64][acol]) = ra1;
    *(uint4*)(&Bs[br][bcol]) = rb0;
    *(uint4*)(&Bs[br + 16][bcol]) = rb1;
    __syncthreads();

    for (int kt = 0; kt < 12; kt++) {
        if (kt < 11) {
            const __nv_bfloat16* ap2 = Ab + (size_t)(row0 + ar) * DIM + (kt + 1) * 32 + acol;
            ra0 = *(const uint4*)(ap2);
            ra1 = *(const uint4*)(ap2 + (size_t)64 * DIM);
            const __nv_bfloat16* bp2 = Bb + (size_t)((kt + 1) * 32 + br) * HW_ + col0 + bcol;
            rb0 = *(const uint4*)(bp2);
            rb1 = *(const uint4*)(bp2 + (size_t)16 * HW_);
        }
        for (int ks = 0; ks < 2; ks++) {
            wx::fragment<wx::matrix_a, 16, 16, 16, __nv_bfloat16, wx::row_major> a[4];
            wx::fragment<wx::matrix_b, 16, 16, 16, __nv_bfloat16, wx::row_major> bf[2];
            for (int i = 0; i < 4; i++)
                wx::load_matrix_sync(a[i], &As[wm * 64 + i * 16][ks * 16], 40);
            for (int j = 0; j < 2; j++)
                wx::load_matrix_sync(bf[j], &Bs[ks * 16][wn * 32 + j * 16], 136);
            for (int i = 0; i < 4; i++)
                for (int j = 0; j < 2; j++)
                    wx::mma_sync(c[i][j], a[i], bf[j], c[i][j]);
        }
        __syncthreads();
        if (kt < 11) {
            *(uint4*)(&As[ar][acol]) = ra0;
            *(uint4*)(&As[ar + 64][acol]) = ra1;
            *(uint4*)(&Bs[br][bcol]) = rb0;
            *(uint4*)(&Bs[br + 16][bcol]) = rb1;
            __syncthreads();
        }
    }

    for (int i = 0; i < 4; i++) {
        wx::store_matrix_sync(&Cs[wid][0][0], c[i][0], 32, wx::mem_row_major);
        wx::store_matrix_sync(&Cs[wid][0][16], c[i][1], 32, wx::mem_row_major);
        __syncwarp();
        int r = lane >> 1;
        int cb = (lane & 1) * 16;
        int gr = row0 + wm * 64 + i * 16 + r;
        int gc = col0 + wn * 32 + cb;
        float bi = bias[gr];
        float* op = ob + (size_t)gr * HW_ + gc;
        const float* rp = rbase;
        if (rp) rp = rbase + (size_t)gr * HW_ + gc;
        for (int q = 0; q < 16; q += 4) {
            float4 v;
            v.x = Cs[wid][r][cb + q] + bi;
            v.y = Cs[wid][r][cb + q + 1] + bi;
            v.z = Cs[wid][r][cb + q + 2] + bi;
            v.w = Cs[wid][r][cb + q + 3] + bi;
            if (rp) {
                float4 xv = *(const float4*)(rp + q);
                v.x += xv.x;
                v.y += xv.y;
                v.z += xv.z;
                v.w += xv.w;
            }
            *(float4*)(op + q) = v;
        }
        __syncwarp();
    }
}

__global__ __launch_bounds__(256) void k1_gemm(const float* __restrict__ b_qkv)
{
    const int b = blockIdx.z;
    const float* nores = 0;
    gemm_body(g_wqb, g_xb + (size_t)b * DIM * HW_, b_qkv, nores,
              g_tmp + (size_t)b * QKV_CH * HW_);
}

__global__ __launch_bounds__(256) void k5_gemm(
    const float* __restrict__ b_proj, const float* __restrict__ x,
    float* __restrict__ out)
{
    const int b = blockIdx.z;
    gemm_body(g_weffb + (size_t)b * DIM * DIM, g_vb + (size_t)b * DIM * HW_,
              b_proj, x + (size_t)b * DIM * HW_, out + (size_t)b * DIM * HW_);
}

__global__ __launch_bounds__(256) void k2_dwconv(
    const float* __restrict__ w_dw, const float* __restrict__ b_dw)
{
    const int ch = blockIdx.y;
    const int b = blockIdx.z;
    const int p = blockIdx.x * blockDim.x + threadIdx.x;
    const int y = p >> 7;
    const int xp = p & 127;
    const float* src = g_tmp + ((size_t)b * QKV_CH + ch) * HW_;

    float wv[9];
    #pragma unroll
    for (int i = 0; i < 9; i++) wv[i] = w_dw[ch * 9 + i];

    float s = b_dw[ch];
    #pragma unroll
    for (int dy = -1; dy <= 1; dy++) {
        int yy = y + dy;
        if (yy < 0 || yy > 127) continue;
        #pragma unroll
        for (int dx = -1; dx <= 1; dx++) {
            int xx = xp + dx;
            if (xx < 0 || xx > 127) continue;
            s += wv[(dy + 1) * 3 + (dx + 1)] * src[yy * 128 + xx];
        }
    }
    if (ch < 768)
        g_qk[((size_t)b * 2 * DIM + ch) * HW_ + p] = s;
    else
        g_vb[((size_t)b * DIM + (ch - 768)) * HW_ + p] = __float2bfloat16(s);
}

__device__ __forceinline__ float warp_red(float v)
{
    v += __shfl_down_sync(0xffffffffu, v, 16);
    v += __shfl_down_sync(0xffffffffu, v, 8);
    v += __shfl_down_sync(0xffffffffu, v, 4);
    v += __shfl_down_sync(0xffffffffu, v, 2);
    v += __shfl_down_sync(0xffffffffu, v, 1);
    return v;
}

__global__ __launch_bounds__(256) void k3_reduce()
{
    const int b = blockIdx.y;
    const float* Q = g_qk + (size_t)b * 2 * DIM * HW_;
    const float* K = Q + (size_t)DIM * HW_;

    float acc[8][8];
    float aq[8];
    float ak[8];
    #pragma unroll
    for (int n = 0; n < 8; n++) {
        aq[n] = 0.f;
        ak[n] = 0.f;
        #pragma unroll
        for (int m = 0; m < 8; m++) acc[n][m] = 0.f;
    }

    const int start = blockIdx.x * blockDim.x + threadIdx.x;
    const int stride = SPLITS * 256;
    for (int i = start; i < DVEC; i += stride) {
        float qv[8];
        float kv[8];
        #pragma unroll
        for (int n = 0; n < 8; n++) {
            qv[n] = Q[(size_t)n * DVEC + i];
            kv[n] = K[(size_t)n * DVEC + i];
        }
        #pragma unroll
        for (int n = 0; n < 8; n++) {
            aq[n] += qv[n] * qv[n];
            ak[n] += kv[n] * kv[n];
            #pragma unroll
            for (int m = 0; m < 8; m++) acc[n][m] += qv[n] * kv[m];
        }
    }

    __shared__ float red[8][80];
    const int lane = threadIdx.x & 31;
    const int wid = threadIdx.x >> 5;
    #pragma unroll
    for (int n = 0; n < 8; n++) {
        #pragma unroll
        for (int m = 0; m < 8; m++) {
            float s = warp_red(acc[n][m]);
            if (lane == 0) red[wid][n * 8 + m] = s;
        }
        float s1 = warp_red(aq[n]);
        if (lane == 0) red[wid][64 + n] = s1;
        float s2 = warp_red(ak[n]);
        if (lane == 0) red[wid][72 + n] = s2;
    }
    __syncthreads();
    if (threadIdx.x < 80) {
        float t = 0.f;
        #pragma unroll
        for (int w = 0; w < 8; w++) t += red[w][threadIdx.x];
        g_part[((size_t)b * SPLITS + blockIdx.x) * 80 + threadIdx.x] = t;
    }
}

__global__ __launch_bounds__(640) void k4a_softmax(const float* __restrict__ temperature)
{
    const int b = blockIdx.x;
    __shared__ float red[80];

    const int e = threadIdx.x >> 3;
    const int j = threadIdx.x & 7;
    float t = 0.f;
    for (int s = j; s < SPLITS; s += 8)
        t += g_part[((size_t)b * SPLITS + s) * 80 + e];
    t += __shfl_down_sync(0xffffffffu, t, 4);
    t += __shfl_down_sync(0xffffffffu, t, 2);
    t += __shfl_down_sync(0xffffffffu, t, 1);
    if (j == 0) red[e] = t;
    __syncthreads();

    if (threadIdx.x < 8) {
        const int n = threadIdx.x;
        const float temp = temperature[0];
        float qn = fmaxf(sqrtf(red[64 + n]), 1e-12f);
        float logit[8];
        float mx = -1e30f;
        #pragma unroll
        for (int m = 0; m < 8; m++) {
            float kn = fmaxf(sqrtf(red[72 + m]), 1e-12f);
            float l = temp * red[n * 8 + m] / (qn * kn);
            logit[m] = l;
            mx = fmaxf(mx, l);
        }
        float sum = 0.f;
        float ex[8];
        #pragma unroll
        for (int m = 0; m < 8; m++) {
            ex[m] = expf(logit[m] - mx);
            sum += ex[m];
        }
        float inv = 1.f / sum;
        #pragma unroll
        for (int m = 0; m < 8; m++) g_attn[b * 64 + n * 8 + m] = ex[m] * inv;
    }
}

__global__ __launch_bounds__(256) void k4b_weff(const float* __restrict__ w_proj)
{
    const int b = blockIdx.y;
    __shared__ float at[64];
    if (threadIdx.x < 64) at[threadIdx.x] = g_attn[b * 64 + threadIdx.x];
    __syncthreads();

    const int idx = blockIdx.x * 256 + threadIdx.x;
    const int co = idx / DIM;
    const int jj = idx % DIM;
    const int m = jj / CC_;
    const int cc = jj % CC_;
    float s = 0.f;
    #pragma unroll
    for (int n = 0; n < 8; n++)
        s += at[n * 8 + m] * __ldg(&w_proj[co * DIM + n * CC_ + cc]);
    g_weffb[(size_t)b * DIM * DIM + idx] = __float2bfloat16(s);
}

extern "C" void kernel_launch(void* const* d_in, const int* in_sizes, int n_in,
                              void* d_out, int out_size)
{
    const float* x = (const float*)d_in[0];
    const float* temp = (const float*)d_in[1];
    const float* w_qkv = (const float*)d_in[2];
    const float* b_qkv = (const float*)d_in[3];
    const float* w_dw = (const float*)d_in[4];
    const float* b_dw = (const float*)d_in[5];
    const float* w_proj = (const float*)d_in[6];
    const float* b_proj = (const float*)d_in[7];
    float* out = (float*)d_out;

    int gcx = 24576;
    int gcw = 432;
    dim3 g1(128, 9, 4);
    dim3 g2(64, 1152, 4);
    dim3 g3(256, 4);
    dim3 g4b(576, 4);
    dim3 g5(128, 3, 4);
    int nb4 = 4;

    kc_conv_x<<<gcx, 256>>>(x);
    kc_conv_w<<<gcw, 256>>>(w_qkv);
    k1_gemm<<<g1, 256>>>(b_qkv);
    k2_dwconv<<<g2, 256>>>(w_dw, b_dw);
    k3_reduce<<<g3, 256>>>();
    k4a_softmax<<<nb4, 640>>>(temp);
    k4b_weff<<<g4b, 256>>>(w_proj);
    k5_gemm<<<g5, 256>>>(b_proj, x, out);
}

// round 5
// speedup vs baseline: 2.9088x; 1.1639x over previous
#include <cuda_runtime.h>
#include <cuda_bf16.h>
#include <mma.h>
#include <math.h>

#define BB 4
#define DIM 384
#define QKV_CH 1152
#define HW_ 16384
#define CC_ 48
#define DVEC 786432
#define SPLITS 256

namespace wx = nvcuda::wmma;

static __device__ __nv_bfloat16 g_tmpb[(size_t)BB * QKV_CH * HW_];
static __device__ float g_qk[(size_t)BB * 2 * DIM * HW_];
static __device__ __nv_bfloat16 g_vb[(size_t)BB * DIM * HW_];
static __device__ __nv_bfloat16 g_xb[(size_t)BB * DIM * HW_];
static __device__ __nv_bfloat16 g_wqb[(size_t)QKV_CH * DIM];
static __device__ float g_part[(size_t)BB * SPLITS * 80];
static __device__ float g_attn[BB * 64];
static __device__ __nv_bfloat16 g_weffb[(size_t)BB * DIM * DIM];

__global__ __launch_bounds__(256) void kc_conv_x(const float* __restrict__ src)
{
    int i = blockIdx.x * 256 + threadIdx.x;
    float4 v = ((const float4*)src)[i];
    ((__nv_bfloat162*)g_xb)[2 * i] = __floats2bfloat162_rn(v.x, v.y);
    ((__nv_bfloat162*)g_xb)[2 * i + 1] = __floats2bfloat162_rn(v.z, v.w);
}

__global__ __launch_bounds__(256) void kc_conv_w(const float* __restrict__ src)
{
    int i = blockIdx.x * 256 + threadIdx.x;
    float4 v = ((const float4*)src)[i];
    ((__nv_bfloat162*)g_wqb)[2 * i] = __floats2bfloat162_rn(v.x, v.y);
    ((__nv_bfloat162*)g_wqb)[2 * i + 1] = __floats2bfloat162_rn(v.z, v.w);
}

__device__ __forceinline__ void gemm_body(
    const __nv_bfloat16* __restrict__ Ab,
    const __nv_bfloat16* __restrict__ Bb,
    const float* __restrict__ bias,
    const float* __restrict__ rbase,
    float* __restrict__ ob,
    __nv_bfloat16* __restrict__ ob16)
{
    const int row0 = blockIdx.y * 128;
    const int col0 = blockIdx.x * 128;

    __shared__ __nv_bfloat16 As[128][40];
    __shared__ __nv_bfloat16 Bs[32][136];
    __shared__ float Cs[8][16][32];

    const int tid = threadIdx.x;
    const int lane = tid & 31;
    const int wid = tid >> 5;
    const int wm = wid & 1;
    const int wn = wid >> 1;

    const int ar = tid >> 2;
    const int acol = (tid & 3) * 8;
    const int br = tid >> 4;
    const int bcol = (tid & 15) * 8;

    wx::fragment<wx::accumulator, 16, 16, 16, float> c[4][2];
    for (int i = 0; i < 4; i++)
        for (int j = 0; j < 2; j++)
            wx::fill_fragment(c[i][j], 0.0f);

    uint4 ra0, ra1, rb0, rb1;

    const __nv_bfloat16* ap = Ab + (size_t)(row0 + ar) * DIM + acol;
    ra0 = *(const uint4*)(ap);
    ra1 = *(const uint4*)(ap + (size_t)64 * DIM);
    const __nv_bfloat16* bp = Bb + (size_t)br * HW_ + col0 + bcol;
    rb0 = *(const uint4*)(bp);
    rb1 = *(const uint4*)(bp + (size_t)16 * HW_);
    *(uint4*)(&As[ar][acol]) = ra0;
    *(uint4*)(&As[ar + 64][acol]) = ra1;
    *(uint4*)(&Bs[br][bcol]) = rb0;
    *(uint4*)(&Bs[br + 16][bcol]) = rb1;
    __syncthreads();

    for (int kt = 0; kt < 12; kt++) {
        if (kt < 11) {
            const __nv_bfloat16* ap2 = Ab + (size_t)(row0 + ar) * DIM + (kt + 1) * 32 + acol;
            ra0 = *(const uint4*)(ap2);
            ra1 = *(const uint4*)(ap2 + (size_t)64 * DIM);
            const __nv_bfloat16* bp2 = Bb + (size_t)((kt + 1) * 32 + br) * HW_ + col0 + bcol;
            rb0 = *(const uint4*)(bp2);
            rb1 = *(const uint4*)(bp2 + (size_t)16 * HW_);
        }
        for (int ks = 0; ks < 2; ks++) {
            wx::fragment<wx::matrix_a, 16, 16, 16, __nv_bfloat16, wx::row_major> a[4];
            wx::fragment<wx::matrix_b, 16, 16, 16, __nv_bfloat16, wx::row_major> bf[2];
            for (int i = 0; i < 4; i++)
                wx::load_matrix_sync(a[i], &As[wm * 64 + i * 16][ks * 16], 40);
            for (int j = 0; j < 2; j++)
                wx::load_matrix_sync(bf[j], &Bs[ks * 16][wn * 32 + j * 16], 136);
            for (int i = 0; i < 4; i++)
                for (int j = 0; j < 2; j++)
                    wx::mma_sync(c[i][j], a[i], bf[j], c[i][j]);
        }
        __syncthreads();
        if (kt < 11) {
            *(uint4*)(&As[ar][acol]) = ra0;
            *(uint4*)(&As[ar + 64][acol]) = ra1;
            *(uint4*)(&Bs[br][bcol]) = rb0;
            *(uint4*)(&Bs[br + 16][bcol]) = rb1;
            __syncthreads();
        }
    }

    for (int i = 0; i < 4; i++) {
        wx::store_matrix_sync(&Cs[wid][0][0], c[i][0], 32, wx::mem_row_major);
        wx::store_matrix_sync(&Cs[wid][0][16], c[i][1], 32, wx::mem_row_major);
        __syncwarp();
        int r = lane >> 1;
        int cb = (lane & 1) * 16;
        int gr = row0 + wm * 64 + i * 16 + r;
        int gc = col0 + wn * 32 + cb;
        float bi = bias[gr];
        for (int q = 0; q < 16; q += 4) {
            float4 v;
            v.x = Cs[wid][r][cb + q] + bi;
            v.y = Cs[wid][r][cb + q + 1] + bi;
            v.z = Cs[wid][r][cb + q + 2] + bi;
            v.w = Cs[wid][r][cb + q + 3] + bi;
            if (ob16) {
                __nv_bfloat162* op16 = (__nv_bfloat162*)(ob16 + (size_t)gr * HW_ + gc);
                op16[(q >> 1)] = __floats2bfloat162_rn(v.x, v.y);
                op16[(q >> 1) + 1] = __floats2bfloat162_rn(v.z, v.w);
            } else {
                if (rbase) {
                    const float* rp = rbase + (size_t)gr * HW_ + gc + q;
                    float4 xv = *(const float4*)(rp);
                    v.x += xv.x;
                    v.y += xv.y;
                    v.z += xv.z;
                    v.w += xv.w;
                }
                *(float4*)(ob + (size_t)gr * HW_ + gc + q) = v;
            }
        }
        __syncwarp();
    }
}

__global__ __launch_bounds__(256) void k1_gemm(const float* __restrict__ b_qkv)
{
    const int b = blockIdx.z;
    const float* nores = 0;
    float* noout = 0;
    gemm_body(g_wqb, g_xb + (size_t)b * DIM * HW_, b_qkv, nores, noout,
              g_tmpb + (size_t)b * QKV_CH * HW_);
}

__global__ __launch_bounds__(256) void k5_gemm(
    const float* __restrict__ b_proj, const float* __restrict__ x,
    float* __restrict__ out)
{
    const int b = blockIdx.z;
    __nv_bfloat16* no16 = 0;
    gemm_body(g_weffb + (size_t)b * DIM * DIM, g_vb + (size_t)b * DIM * HW_,
              b_proj, x + (size_t)b * DIM * HW_, out + (size_t)b * DIM * HW_, no16);
}

__global__ __launch_bounds__(256) void k2_dwconv(
    const float* __restrict__ w_dw, const float* __restrict__ b_dw)
{
    const int ch = blockIdx.y;
    const int b = blockIdx.z;
    const int y0 = blockIdx.x * 16;

    __shared__ float s[18][128];
    const __nv_bfloat16* src = g_tmpb + ((size_t)b * QKV_CH + ch) * HW_;

    for (int idx = threadIdx.x; idx < 288; idx += 256) {
        int rr = idx >> 4;
        int c8 = (idx & 15) * 8;
        int gy = y0 - 1 + rr;
        float* drow = &s[rr][c8];
        if (gy < 0 || gy > 127) {
            drow[0] = 0.f; drow[1] = 0.f; drow[2] = 0.f; drow[3] = 0.f;
            drow[4] = 0.f; drow[5] = 0.f; drow[6] = 0.f; drow[7] = 0.f;
        } else {
            uint4 v = *(const uint4*)(src + gy * 128 + c8);
            __nv_bfloat162 p0 = *(__nv_bfloat162*)(&v.x);
            __nv_bfloat162 p1 = *(__nv_bfloat162*)(&v.y);
            __nv_bfloat162 p2 = *(__nv_bfloat162*)(&v.z);
            __nv_bfloat162 p3 = *(__nv_bfloat162*)(&v.w);
            float2 f0 = __bfloat1622float2(p0);
            float2 f1 = __bfloat1622float2(p1);
            float2 f2 = __bfloat1622float2(p2);
            float2 f3 = __bfloat1622float2(p3);
            drow[0] = f0.x; drow[1] = f0.y; drow[2] = f1.x; drow[3] = f1.y;
            drow[4] = f2.x; drow[5] = f2.y; drow[6] = f3.x; drow[7] = f3.y;
        }
    }
    __syncthreads();

    float wv[9];
    #pragma unroll
    for (int i = 0; i < 9; i++) wv[i] = w_dw[ch * 9 + i];
    float bi = b_dw[ch];

    const int r = threadIdx.x >> 4;
    const int x0 = (threadIdx.x & 15) * 8;

    float top[10];
    float mid[10];
    float bot[10];
    #pragma unroll
    for (int j = 0; j < 10; j++) {
        int xx = x0 - 1 + j;
        bool ok = (xx >= 0) && (xx < 128);
        top[j] = ok ? s[r][xx] : 0.f;
        mid[j] = ok ? s[r + 1][xx] : 0.f;
        bot[j] = ok ? s[r + 2][xx] : 0.f;
    }

    float o[8];
    #pragma unroll
    for (int i = 0; i < 8; i++) {
        float t = bi;
        t += wv[0] * top[i];
        t += wv[1] * top[i + 1];
        t += wv[2] * top[i + 2];
        t += wv[3] * mid[i];
        t += wv[4] * mid[i + 1];
        t += wv[5] * mid[i + 2];
        t += wv[6] * bot[i];
        t += wv[7] * bot[i + 1];
        t += wv[8] * bot[i + 2];
        o[i] = t;
    }

    const int p = (y0 + r) * 128 + x0;
    if (ch < 768) {
        float* dst = g_qk + ((size_t)b * 2 * DIM + ch) * HW_ + p;
        float4 v0;
        v0.x = o[0]; v0.y = o[1]; v0.z = o[2]; v0.w = o[3];
        float4 v1;
        v1.x = o[4]; v1.y = o[5]; v1.z = o[6]; v1.w = o[7];
        *(float4*)(dst) = v0;
        *(float4*)(dst + 4) = v1;
    } else {
        __nv_bfloat162* dst = (__nv_bfloat162*)(g_vb + ((size_t)b * DIM + (ch - 768)) * HW_ + p);
        dst[0] = __floats2bfloat162_rn(o[0], o[1]);
        dst[1] = __floats2bfloat162_rn(o[2], o[3]);
        dst[2] = __floats2bfloat162_rn(o[4], o[5]);
        dst[3] = __floats2bfloat162_rn(o[6], o[7]);
    }
}

__device__ __forceinline__ float warp_red(float v)
{
    v += __shfl_down_sync(0xffffffffu, v, 16);
    v += __shfl_down_sync(0xffffffffu, v, 8);
    v += __shfl_down_sync(0xffffffffu, v, 4);
    v += __shfl_down_sync(0xffffffffu, v, 2);
    v += __shfl_down_sync(0xffffffffu, v, 1);
    return v;
}

__global__ __launch_bounds__(256) void k3_reduce()
{
    const int b = blockIdx.y;
    const float* Q = g_qk + (size_t)b * 2 * DIM * HW_;
    const float* K = Q + (size_t)DIM * HW_;

    float acc[8][8];
    float aq[8];
    float ak[8];
    #pragma unroll
    for (int n = 0; n < 8; n++) {
        aq[n] = 0.f;
        ak[n] = 0.f;
        #pragma unroll
        for (int m = 0; m < 8; m++) acc[n][m] = 0.f;
    }

    const int start = blockIdx.x * blockDim.x + threadIdx.x;
    const int stride = SPLITS * 256;
    for (int i = start; i < DVEC; i += stride) {
        float qv[8];
        float kv[8];
        #pragma unroll
        for (int n = 0; n < 8; n++) {
            qv[n] = Q[(size_t)n * DVEC + i];
            kv[n] = K[(size_t)n * DVEC + i];
        }
        #pragma unroll
        for (int n = 0; n < 8; n++) {
            aq[n] += qv[n] * qv[n];
            ak[n] += kv[n] * kv[n];
            #pragma unroll
            for (int m = 0; m < 8; m++) acc[n][m] += qv[n] * kv[m];
        }
    }

    __shared__ float red[8][80];
    const int lane = threadIdx.x & 31;
    const int wid = threadIdx.x >> 5;
    #pragma unroll
    for (int n = 0; n < 8; n++) {
        #pragma unroll
        for (int m = 0; m < 8; m++) {
            float s = warp_red(acc[n][m]);
            if (lane == 0) red[wid][n * 8 + m] = s;
        }
        float s1 = warp_red(aq[n]);
        if (lane == 0) red[wid][64 + n] = s1;
        float s2 = warp_red(ak[n]);
        if (lane == 0) red[wid][72 + n] = s2;
    }
    __syncthreads();
    if (threadIdx.x < 80) {
        float t = 0.f;
        #pragma unroll
        for (int w = 0; w < 8; w++) t += red[w][threadIdx.x];
        g_part[((size_t)b * SPLITS + blockIdx.x) * 80 + threadIdx.x] = t;
    }
}

__global__ __launch_bounds__(640) void k4a_softmax(const float* __restrict__ temperature)
{
    const int b = blockIdx.x;
    __shared__ float red[80];

    const int e = threadIdx.x >> 3;
    const int j = threadIdx.x & 7;
    float t = 0.f;
    for (int s = j; s < SPLITS; s += 8)
        t += g_part[((size_t)b * SPLITS + s) * 80 + e];
    t += __shfl_down_sync(0xffffffffu, t, 4);
    t += __shfl_down_sync(0xffffffffu, t, 2);
    t += __shfl_down_sync(0xffffffffu, t, 1);
    if (j == 0) red[e] = t;
    __syncthreads();

    if (threadIdx.x < 8) {
        const int n = threadIdx.x;
        const float temp = temperature[0];
        float qn = fmaxf(sqrtf(red[64 + n]), 1e-12f);
        float logit[8];
        float mx = -1e30f;
        #pragma unroll
        for (int m = 0; m < 8; m++) {
            float kn = fmaxf(sqrtf(red[72 + m]), 1e-12f);
            float l = temp * red[n * 8 + m] / (qn * kn);
            logit[m] = l;
            mx = fmaxf(mx, l);
        }
        float sum = 0.f;
        float ex[8];
        #pragma unroll
        for (int m = 0; m < 8; m++) {
            ex[m] = expf(logit[m] - mx);
            sum += ex[m];
        }
        float inv = 1.f / sum;
        #pragma unroll
        for (int m = 0; m < 8; m++) g_attn[b * 64 + n * 8 + m] = ex[m] * inv;
    }
}

__global__ __launch_bounds__(256) void k4b_weff(const float* __restrict__ w_proj)
{
    const int b = blockIdx.y;
    __shared__ float at[64];
    if (threadIdx.x < 64) at[threadIdx.x] = g_attn[b * 64 + threadIdx.x];
    __syncthreads();

    const int idx = blockIdx.x * 256 + threadIdx.x;
    const int co = idx / DIM;
    const int jj = idx % DIM;
    const int m = jj / CC_;
    const int cc = jj % CC_;
    float s = 0.f;
    #pragma unroll
    for (int n = 0; n < 8; n++)
        s += at[n * 8 + m] * __ldg(&w_proj[co * DIM + n * CC_ + cc]);
    g_weffb[(size_t)b * DIM * DIM + idx] = __float2bfloat16(s);
}

extern "C" void kernel_launch(void* const* d_in, const int* in_sizes, int n_in,
                              void* d_out, int out_size)
{
    const float* x = (const float*)d_in[0];
    const float* temp = (const float*)d_in[1];
    const float* w_qkv = (const float*)d_in[2];
    const float* b_qkv = (const float*)d_in[3];
    const float* w_dw = (const float*)d_in[4];
    const float* b_dw = (const float*)d_in[5];
    const float* w_proj = (const float*)d_in[6];
    const float* b_proj = (const float*)d_in[7];
    float* out = (float*)d_out;

    int gcx = 24576;
    int gcw = 432;
    dim3 g1(128, 9, 4);
    dim3 g2(8, 1152, 4);
    dim3 g3(256, 4);
    dim3 g4b(576, 4);
    dim3 g5(128, 3, 4);
    int nb4 = 4;

    kc_conv_x<<<gcx, 256>>>(x);
    kc_conv_w<<<gcw, 256>>>(w_qkv);
    k1_gemm<<<g1, 256>>>(b_qkv);
    k2_dwconv<<<g2, 256>>>(w_dw, b_dw);
    k3_reduce<<<g3, 256>>>();
    k4a_softmax<<<nb4, 640>>>(temp);
    k4b_weff<<<g4b, 256>>>(w_proj);
    k5_gemm<<<g5, 256>>>(b_proj, x, out);
}

// round 6
// speedup vs baseline: 3.1411x; 1.0798x over previous
#include <cuda_runtime.h>
#include <cuda_bf16.h>
#include <mma.h>
#include <math.h>

#define BB 4
#define DIM 384
#define QKV_CH 1152
#define HW_ 16384
#define CC_ 48
#define NPART 768

namespace wx = nvcuda::wmma;

static __device__ __nv_bfloat16 g_tmpb[(size_t)BB * QKV_CH * HW_];
static __device__ __nv_bfloat16 g_vb[(size_t)BB * DIM * HW_];
static __device__ __nv_bfloat16 g_xb[(size_t)BB * DIM * HW_];
static __device__ __nv_bfloat16 g_wqb[(size_t)QKV_CH * DIM];
static __device__ float g_part[(size_t)BB * NPART * 80];
static __device__ float g_attn[BB * 64];
static __device__ __nv_bfloat16 g_weffb[(size_t)BB * DIM * DIM];

__global__ __launch_bounds__(256) void kc_conv_x(const float* __restrict__ src)
{
    int i = blockIdx.x * 256 + threadIdx.x;
    float4 v = ((const float4*)src)[i];
    ((__nv_bfloat162*)g_xb)[2 * i] = __floats2bfloat162_rn(v.x, v.y);
    ((__nv_bfloat162*)g_xb)[2 * i + 1] = __floats2bfloat162_rn(v.z, v.w);
}

__global__ __launch_bounds__(256) void kc_conv_w(const float* __restrict__ src)
{
    int i = blockIdx.x * 256 + threadIdx.x;
    float4 v = ((const float4*)src)[i];
    ((__nv_bfloat162*)g_wqb)[2 * i] = __floats2bfloat162_rn(v.x, v.y);
    ((__nv_bfloat162*)g_wqb)[2 * i + 1] = __floats2bfloat162_rn(v.z, v.w);
}

__device__ __forceinline__ void gemm_body(
    const __nv_bfloat16* __restrict__ Ab,
    const __nv_bfloat16* __restrict__ Bb,
    const float* __restrict__ bias,
    const float* __restrict__ rbase,
    float* __restrict__ ob,
    __nv_bfloat16* __restrict__ ob16)
{
    const int row0 = blockIdx.y * 128;
    const int col0 = blockIdx.x * 128;

    __shared__ __nv_bfloat16 As[128][40];
    __shared__ __nv_bfloat16 Bs[32][136];
    __shared__ float Cs[8][16][32];

    const int tid = threadIdx.x;
    const int lane = tid & 31;
    const int wid = tid >> 5;
    const int wm = wid & 1;
    const int wn = wid >> 1;

    const int ar = tid >> 2;
    const int acol = (tid & 3) * 8;
    const int br = tid >> 4;
    const int bcol = (tid & 15) * 8;

    wx::fragment<wx::accumulator, 16, 16, 16, float> c[4][2];
    for (int i = 0; i < 4; i++)
        for (int j = 0; j < 2; j++)
            wx::fill_fragment(c[i][j], 0.0f);

    uint4 ra0, ra1, rb0, rb1;

    const __nv_bfloat16* ap = Ab + (size_t)(row0 + ar) * DIM + acol;
    ra0 = *(const uint4*)(ap);
    ra1 = *(const uint4*)(ap + (size_t)64 * DIM);
    const __nv_bfloat16* bp = Bb + (size_t)br * HW_ + col0 + bcol;
    rb0 = *(const uint4*)(bp);
    rb1 = *(const uint4*)(bp + (size_t)16 * HW_);
    *(uint4*)(&As[ar][acol]) = ra0;
    *(uint4*)(&As[ar + 64][acol]) = ra1;
    *(uint4*)(&Bs[br][bcol]) = rb0;
    *(uint4*)(&Bs[br + 16][bcol]) = rb1;
    __syncthreads();

    for (int kt = 0; kt < 12; kt++) {
        if (kt < 11) {
            const __nv_bfloat16* ap2 = Ab + (size_t)(row0 + ar) * DIM + (kt + 1) * 32 + acol;
            ra0 = *(const uint4*)(ap2);
            ra1 = *(const uint4*)(ap2 + (size_t)64 * DIM);
            const __nv_bfloat16* bp2 = Bb + (size_t)((kt + 1) * 32 + br) * HW_ + col0 + bcol;
            rb0 = *(const uint4*)(bp2);
            rb1 = *(const uint4*)(bp2 + (size_t)16 * HW_);
        }
        for (int ks = 0; ks < 2; ks++) {
            wx::fragment<wx::matrix_a, 16, 16, 16, __nv_bfloat16, wx::row_major> a[4];
            wx::fragment<wx::matrix_b, 16, 16, 16, __nv_bfloat16, wx::row_major> bf[2];
            for (int i = 0; i < 4; i++)
                wx::load_matrix_sync(a[i], &As[wm * 64 + i * 16][ks * 16], 40);
            for (int j = 0; j < 2; j++)
                wx::load_matrix_sync(bf[j], &Bs[ks * 16][wn * 32 + j * 16], 136);
            for (int i = 0; i < 4; i++)
                for (int j = 0; j < 2; j++)
                    wx::mma_sync(c[i][j], a[i], bf[j], c[i][j]);
        }
        __syncthreads();
        if (kt < 11) {
            *(uint4*)(&As[ar][acol]) = ra0;
            *(uint4*)(&As[ar + 64][acol]) = ra1;
            *(uint4*)(&Bs[br][bcol]) = rb0;
            *(uint4*)(&Bs[br + 16][bcol]) = rb1;
            __syncthreads();
        }
    }

    for (int i = 0; i < 4; i++) {
        wx::store_matrix_sync(&Cs[wid][0][0], c[i][0], 32, wx::mem_row_major);
        wx::store_matrix_sync(&Cs[wid][0][16], c[i][1], 32, wx::mem_row_major);
        __syncwarp();
        int r = lane >> 1;
        int cb = (lane & 1) * 16;
        int gr = row0 + wm * 64 + i * 16 + r;
        int gc = col0 + wn * 32 + cb;
        float bi = bias[gr];
        for (int q = 0; q < 16; q += 4) {
            float4 v;
            v.x = Cs[wid][r][cb + q] + bi;
            v.y = Cs[wid][r][cb + q + 1] + bi;
            v.z = Cs[wid][r][cb + q + 2] + bi;
            v.w = Cs[wid][r][cb + q + 3] + bi;
            if (ob16) {
                __nv_bfloat162* op16 = (__nv_bfloat162*)(ob16 + (size_t)gr * HW_ + gc);
                op16[(q >> 1)] = __floats2bfloat162_rn(v.x, v.y);
                op16[(q >> 1) + 1] = __floats2bfloat162_rn(v.z, v.w);
            } else {
                if (rbase) {
                    const float* rp = rbase + (size_t)gr * HW_ + gc + q;
                    float4 xv = *(const float4*)(rp);
                    v.x += xv.x;
                    v.y += xv.y;
                    v.z += xv.z;
                    v.w += xv.w;
                }
                *(float4*)(ob + (size_t)gr * HW_ + gc + q) = v;
            }
        }
        __syncwarp();
    }
}

__global__ __launch_bounds__(256) void k1_gemm(const float* __restrict__ b_qkv)
{
    const int b = blockIdx.z;
    const float* nores = 0;
    float* noout = 0;
    gemm_body(g_wqb, g_xb + (size_t)b * DIM * HW_, b_qkv, nores, noout,
              g_tmpb + (size_t)b * QKV_CH * HW_);
}

__global__ __launch_bounds__(256) void k5_gemm(
    const float* __restrict__ b_proj, const float* __restrict__ x,
    float* __restrict__ out)
{
    const int b = blockIdx.z;
    __nv_bfloat16* no16 = 0;
    gemm_body(g_weffb + (size_t)b * DIM * DIM, g_vb + (size_t)b * DIM * HW_,
              b_proj, x + (size_t)b * DIM * HW_, out + (size_t)b * DIM * HW_, no16);
}

__device__ __forceinline__ float warp_red(float v)
{
    v += __shfl_down_sync(0xffffffffu, v, 16);
    v += __shfl_down_sync(0xffffffffu, v, 8);
    v += __shfl_down_sync(0xffffffffu, v, 4);
    v += __shfl_down_sync(0xffffffffu, v, 2);
    v += __shfl_down_sync(0xffffffffu, v, 1);
    return v;
}

// Fused dwconv(q,k) + Gram/norm partial reductions.
// block = (strip of 8 rows, cc, b). 16 channels: q_n = n*48+cc, k_m = 384+m*48+cc.
// smem plane per channel: 10 rows x pitch 144 bf16, data at col offset 8, halo zeros.
__global__ __launch_bounds__(256) void k2qk(
    const float* __restrict__ w_dw, const float* __restrict__ b_dw)
{
    const int b = blockIdx.z;
    const int cc = blockIdx.y;
    const int strip = blockIdx.x;
    const int y0 = strip * 8;

    __shared__ __align__(16) char sbuf[46080];
    __shared__ float sw[16][9];
    __shared__ float sbias[16];

    __nv_bfloat16* sm = (__nv_bfloat16*)sbuf;
    const __nv_bfloat16* tb = g_tmpb + (size_t)b * QKV_CH * HW_;

    for (int idx = threadIdx.x; idx < 2560; idx += 256) {
        int ch = idx / 160;
        int rem = idx - ch * 160;
        int row = rem >> 4;
        int u = rem & 15;
        int gy = y0 - 1 + row;
        uint4 v;
        v.x = 0u; v.y = 0u; v.z = 0u; v.w = 0u;
        if (gy >= 0 && gy < 128) {
            int chg = ch * 48 + cc;
            if (ch >= 8) chg = 384 + (ch - 8) * 48 + cc;
            v = *(const uint4*)(tb + (size_t)chg * HW_ + gy * 128 + u * 8);
        }
        *(uint4*)(sm + ((ch * 10 + row) * 144 + 8 + u * 8)) = v;
    }
    for (int idx = threadIdx.x; idx < 320; idx += 256) {
        int ch = idx / 20;
        int rem = idx - ch * 20;
        int row = rem >> 1;
        int col = 7;
        if (rem & 1) col = 136;
        sm[(ch * 10 + row) * 144 + col] = __float2bfloat16(0.f);
    }
    if (threadIdx.x < 144) {
        int ci = threadIdx.x / 9;
        int j = threadIdx.x - ci * 9;
        int chg = ci * 48 + cc;
        if (ci >= 8) chg = 384 + (ci - 8) * 48 + cc;
        sw[ci][j] = w_dw[chg * 9 + j];
    }
    if (threadIdx.x >= 144 && threadIdx.x < 160) {
        int ci = threadIdx.x - 144;
        int chg = ci * 48 + cc;
        if (ci >= 8) chg = 384 + (ci - 8) * 48 + cc;
        sbias[ci] = b_dw[chg];
    }
    __syncthreads();

    const int r = threadIdx.x >> 5;
    const int x0 = (threadIdx.x & 31) * 4;

    float acc[8][8];
    float aq[8];
    float ak[8];
    float qo[8][4];
    #pragma unroll
    for (int n = 0; n < 8; n++) {
        aq[n] = 0.f;
        ak[n] = 0.f;
        #pragma unroll
        for (int m = 0; m < 8; m++) acc[n][m] = 0.f;
    }

    #pragma unroll
    for (int n = 0; n < 8; n++) {
        float v0[8];
        float v1[8];
        float v2[8];
        #pragma unroll
        for (int j = 0; j < 4; j++) {
            int base0 = (n * 10 + r) * 144 + 6 + x0 + 2 * j;
            float2 f0 = __bfloat1622float2(*(const __nv_bfloat162*)(sm + base0));
            float2 f1 = __bfloat1622float2(*(const __nv_bfloat162*)(sm + base0 + 144));
            float2 f2 = __bfloat1622float2(*(const __nv_bfloat162*)(sm + base0 + 288));
            v0[2 * j] = f0.x; v0[2 * j + 1] = f0.y;
            v1[2 * j] = f1.x; v1[2 * j + 1] = f1.y;
            v2[2 * j] = f2.x; v2[2 * j + 1] = f2.y;
        }
        float bi = sbias[n];
        #pragma unroll
        for (int i = 0; i < 4; i++) {
            float o = bi;
            o += sw[n][0] * v0[1 + i];
            o += sw[n][1] * v0[2 + i];
            o += sw[n][2] * v0[3 + i];
            o += sw[n][3] * v1[1 + i];
            o += sw[n][4] * v1[2 + i];
            o += sw[n][5] * v1[3 + i];
            o += sw[n][6] * v2[1 + i];
            o += sw[n][7] * v2[2 + i];
            o += sw[n][8] * v2[3 + i];
            qo[n][i] = o;
            aq[n] += o * o;
        }
    }

    #pragma unroll
    for (int m = 0; m < 8; m++) {
        float v0[8];
        float v1[8];
        float v2[8];
        #pragma unroll
        for (int j = 0; j < 4; j++) {
            int base0 = ((8 + m) * 10 + r) * 144 + 6 + x0 + 2 * j;
            float2 f0 = __bfloat1622float2(*(const __nv_bfloat162*)(sm + base0));
            float2 f1 = __bfloat1622float2(*(const __nv_bfloat162*)(sm + base0 + 144));
            float2 f2 = __bfloat1622float2(*(const __nv_bfloat162*)(sm + base0 + 288));
            v0[2 * j] = f0.x; v0[2 * j + 1] = f0.y;
            v1[2 * j] = f1.x; v1[2 * j + 1] = f1.y;
            v2[2 * j] = f2.x; v2[2 * j + 1] = f2.y;
        }
        float bi = sbias[8 + m];
        float ko[4];
        #pragma unroll
        for (int i = 0; i < 4; i++) {
            float o = bi;
            o += sw[8 + m][0] * v0[1 + i];
            o += sw[8 + m][1] * v0[2 + i];
            o += sw[8 + m][2] * v0[3 + i];
            o += sw[8 + m][3] * v1[1 + i];
            o += sw[8 + m][4] * v1[2 + i];
            o += sw[8 + m][5] * v1[3 + i];
            o += sw[8 + m][6] * v2[1 + i];
            o += sw[8 + m][7] * v2[2 + i];
            o += sw[8 + m][8] * v2[3 + i];
            ko[i] = o;
            ak[m] += o * o;
        }
        #pragma unroll
        for (int n = 0; n < 8; n++) {
            #pragma unroll
            for (int i = 0; i < 4; i++) acc[n][m] += qo[n][i] * ko[i];
        }
    }

    __syncthreads();
    float* red = (float*)sbuf;
    const int lane = threadIdx.x & 31;
    const int wid = threadIdx.x >> 5;
    #pragma unroll
    for (int n = 0; n < 8; n++) {
        #pragma unroll
        for (int m = 0; m < 8; m++) {
            float s = warp_red(acc[n][m]);
            if (lane == 0) red[wid * 80 + n * 8 + m] = s;
        }
        float s1 = warp_red(aq[n]);
        if (lane == 0) red[wid * 80 + 64 + n] = s1;
        float s2 = warp_red(ak[n]);
        if (lane == 0) red[wid * 80 + 72 + n] = s2;
    }
    __syncthreads();
    if (threadIdx.x < 80) {
        float t = 0.f;
        #pragma unroll
        for (int w = 0; w < 8; w++) t += red[w * 80 + threadIdx.x];
        g_part[((size_t)b * NPART + cc * 16 + strip) * 80 + threadIdx.x] = t;
    }
}

// dwconv for v channels only -> g_vb (bf16). block = (strip of 16 rows, v-ch, b)
__global__ __launch_bounds__(256) void k2v(
    const float* __restrict__ w_dw, const float* __restrict__ b_dw)
{
    const int chv = blockIdx.y;
    const int ch = 768 + chv;
    const int b = blockIdx.z;
    const int y0 = blockIdx.x * 16;

    __shared__ __align__(16) __nv_bfloat16 smv[18 * 144];
    const __nv_bfloat16* src = g_tmpb + ((size_t)b * QKV_CH + ch) * HW_;

    for (int idx = threadIdx.x; idx < 288; idx += 256) {
        int row = idx >> 4;
        int u = idx & 15;
        int gy = y0 - 1 + row;
        uint4 v;
        v.x = 0u; v.y = 0u; v.z = 0u; v.w = 0u;
        if (gy >= 0 && gy < 128) v = *(const uint4*)(src + gy * 128 + u * 8);
        *(uint4*)(smv + (row * 144 + 8 + u * 8)) = v;
    }
    if (threadIdx.x < 36) {
        int row = threadIdx.x >> 1;
        int col = 7;
        if (threadIdx.x & 1) col = 136;
        smv[row * 144 + col] = __float2bfloat16(0.f);
    }
    __syncthreads();

    float wv[9];
    #pragma unroll
    for (int i = 0; i < 9; i++) wv[i] = w_dw[ch * 9 + i];
    float bi = b_dw[ch];

    const int r = threadIdx.x >> 4;
    const int x0 = (threadIdx.x & 15) * 8;

    float v0[12];
    float v1[12];
    float v2[12];
    #pragma unroll
    for (int j = 0; j < 6; j++) {
        int base0 = r * 144 + 6 + x0 + 2 * j;
        float2 f0 = __bfloat1622float2(*(const __nv_bfloat162*)(smv + base0));
        float2 f1 = __bfloat1622float2(*(const __nv_bfloat162*)(smv + base0 + 144));
        float2 f2 = __bfloat1622float2(*(const __nv_bfloat162*)(smv + base0 + 288));
        v0[2 * j] = f0.x; v0[2 * j + 1] = f0.y;
        v1[2 * j] = f1.x; v1[2 * j + 1] = f1.y;
        v2[2 * j] = f2.x; v2[2 * j + 1] = f2.y;
    }

    float o[8];
    #pragma unroll
    for (int i = 0; i < 8; i++) {
        float t = bi;
        t += wv[0] * v0[1 + i];
        t += wv[1] * v0[2 + i];
        t += wv[2] * v0[3 + i];
        t += wv[3] * v1[1 + i];
        t += wv[4] * v1[2 + i];
        t += wv[5] * v1[3 + i];
        t += wv[6] * v2[1 + i];
        t += wv[7] * v2[2 + i];
        t += wv[8] * v2[3 + i];
        o[i] = t;
    }

    const int p = (y0 + r) * 128 + x0;
    __nv_bfloat162* dst = (__nv_bfloat162*)(g_vb + ((size_t)b * DIM + chv) * HW_ + p);
    dst[0] = __floats2bfloat162_rn(o[0], o[1]);
    dst[1] = __floats2bfloat162_rn(o[2], o[3]);
    dst[2] = __floats2bfloat162_rn(o[4], o[5]);
    dst[3] = __floats2bfloat162_rn(o[6], o[7]);
}

__global__ __launch_bounds__(640) void k4a_softmax(const float* __restrict__ temperature)
{
    const int b = blockIdx.x;
    __shared__ float red[80];

    const int e = threadIdx.x >> 3;
    const int j = threadIdx.x & 7;
    float t = 0.f;
    for (int s = j; s < NPART; s += 8)
        t += g_part[((size_t)b * NPART + s) * 80 + e];
    t += __shfl_down_sync(0xffffffffu, t, 4);
    t += __shfl_down_sync(0xffffffffu, t, 2);
    t += __shfl_down_sync(0xffffffffu, t, 1);
    if (j == 0) red[e] = t;
    __syncthreads();

    if (threadIdx.x < 8) {
        const int n = threadIdx.x;
        const float temp = temperature[0];
        float qn = fmaxf(sqrtf(red[64 + n]), 1e-12f);
        float logit[8];
        float mx = -1e30f;
        #pragma unroll
        for (int m = 0; m < 8; m++) {
            float kn = fmaxf(sqrtf(red[72 + m]), 1e-12f);
            float l = temp * red[n * 8 + m] / (qn * kn);
            logit[m] = l;
            mx = fmaxf(mx, l);
        }
        float sum = 0.f;
        float ex[8];
        #pragma unroll
        for (int m = 0; m < 8; m++) {
            ex[m] = expf(logit[m] - mx);
            sum += ex[m];
        }
        float inv = 1.f / sum;
        #pragma unroll
        for (int m = 0; m < 8; m++) g_attn[b * 64 + n * 8 + m] = ex[m] * inv;
    }
}

__global__ __launch_bounds__(256) void k4b_weff(const float* __restrict__ w_proj)
{
    const int b = blockIdx.y;
    __shared__ float at[64];
    if (threadIdx.x < 64) at[threadIdx.x] = g_attn[b * 64 + threadIdx.x];
    __syncthreads();

    const int idx = blockIdx.x * 256 + threadIdx.x;
    const int co = idx / DIM;
    const int jj = idx % DIM;
    const int m = jj / CC_;
    const int cc = jj % CC_;
    float s = 0.f;
    #pragma unroll
    for (int n = 0; n < 8; n++)
        s += at[n * 8 + m] * __ldg(&w_proj[co * DIM + n * CC_ + cc]);
    g_weffb[(size_t)b * DIM * DIM + idx] = __float2bfloat16(s);
}

extern "C" void kernel_launch(void* const* d_in, const int* in_sizes, int n_in,
                              void* d_out, int out_size)
{
    const float* x = (const float*)d_in[0];
    const float* temp = (const float*)d_in[1];
    const float* w_qkv = (const float*)d_in[2];
    const float* b_qkv = (const float*)d_in[3];
    const float* w_dw = (const float*)d_in[4];
    const float* b_dw = (const float*)d_in[5];
    const float* w_proj = (const float*)d_in[6];
    const float* b_proj = (const float*)d_in[7];
    float* out = (float*)d_out;

    int gcx = 24576;
    int gcw = 432;
    dim3 g1(128, 9, 4);
    dim3 gqk(16, 48, 4);
    dim3 gv(8, 384, 4);
    dim3 g4b(576, 4);
    dim3 g5(128, 3, 4);
    int nb4 = 4;

    kc_conv_x<<<gcx, 256>>>(x);
    kc_conv_w<<<gcw, 256>>>(w_qkv);
    k1_gemm<<<g1, 256>>>(b_qkv);
    k2qk<<<gqk, 256>>>(w_dw, b_dw);
    k2v<<<gv, 256>>>(w_dw, b_dw);
    k4a_softmax<<<nb4, 640>>>(temp);
    k4b_weff<<<g4b, 256>>>(w_proj);
    k5_gemm<<<g5, 256>>>(b_proj, x, out);
}

// round 7
// speedup vs baseline: 3.3034x; 1.0517x over previous
#include <cuda_runtime.h>
#include <cuda_bf16.h>
#include <cuda_pipeline.h>
#include <mma.h>
#include <math.h>

#define BB 4
#define DIM 384
#define QKV_CH 1152
#define HW_ 16384
#define CC_ 48
#define NPART 768

namespace wx = nvcuda::wmma;

static __device__ __nv_bfloat16 g_tmpb[(size_t)BB * QKV_CH * HW_];
static __device__ __nv_bfloat16 g_vb[(size_t)BB * DIM * HW_];
static __device__ __nv_bfloat16 g_xb[(size_t)BB * DIM * HW_];
static __device__ __nv_bfloat16 g_wqb[(size_t)QKV_CH * DIM];
static __device__ float g_part[(size_t)BB * NPART * 80];
static __device__ float g_attn[BB * 64];
static __device__ __nv_bfloat16 g_weffb[(size_t)BB * DIM * DIM];

__global__ __launch_bounds__(256) void kc_conv_x(const float* __restrict__ src)
{
    int i = blockIdx.x * 256 + threadIdx.x;
    float4 v = ((const float4*)src)[i];
    ((__nv_bfloat162*)g_xb)[2 * i] = __floats2bfloat162_rn(v.x, v.y);
    ((__nv_bfloat162*)g_xb)[2 * i + 1] = __floats2bfloat162_rn(v.z, v.w);
}

__global__ __launch_bounds__(256) void kc_conv_w(const float* __restrict__ src)
{
    int i = blockIdx.x * 256 + threadIdx.x;
    float4 v = ((const float4*)src)[i];
    ((__nv_bfloat162*)g_wqb)[2 * i] = __floats2bfloat162_rn(v.x, v.y);
    ((__nv_bfloat162*)g_wqb)[2 * i + 1] = __floats2bfloat162_rn(v.z, v.w);
}

// Double-buffered cp.async bf16 wmma GEMM.
// Buffer layout per stage (18944 B): A 128x32 (pitch 40 bf16, 10240 B),
// B 32x128 (pitch 136 bf16, 8704 B). Two stages = 37888 B static smem.
// Epilogue Cs (16 KB) aliases the buffers after the final barrier.
__device__ __forceinline__ void gemm_body(
    const __nv_bfloat16* __restrict__ Ab,
    const __nv_bfloat16* __restrict__ Bb,
    const float* __restrict__ bias,
    const float* __restrict__ rbase,
    float* __restrict__ ob,
    __nv_bfloat16* __restrict__ ob16)
{
    const int row0 = blockIdx.y * 128;
    const int col0 = blockIdx.x * 128;

    __shared__ __align__(16) char sbuf[37888];

    const int tid = threadIdx.x;
    const int lane = tid & 31;
    const int wid = tid >> 5;
    const int wm = wid & 1;
    const int wn = wid >> 1;

    const int ar = tid >> 2;
    const int acol = (tid & 3) * 8;
    const int br = tid >> 4;
    const int bcol = (tid & 15) * 8;

    char* a_dst0 = sbuf + ar * 80 + acol * 2;
    char* a_dst1 = sbuf + (ar + 64) * 80 + acol * 2;
    char* b_dst0 = sbuf + 10240 + br * 272 + bcol * 2;
    char* b_dst1 = sbuf + 10240 + (br + 16) * 272 + bcol * 2;

    wx::fragment<wx::accumulator, 16, 16, 16, float> c[4][2];
    for (int i = 0; i < 4; i++)
        for (int j = 0; j < 2; j++)
            wx::fill_fragment(c[i][j], 0.0f);

    const __nv_bfloat16* a_src0 = Ab + (size_t)(row0 + ar) * DIM + acol;
    const __nv_bfloat16* a_src1 = a_src0 + (size_t)64 * DIM;
    const __nv_bfloat16* b_src0 = Bb + (size_t)br * HW_ + col0 + bcol;
    const __nv_bfloat16* b_src1 = b_src0 + (size_t)16 * HW_;

    __pipeline_memcpy_async(a_dst0, a_src0, 16);
    __pipeline_memcpy_async(a_dst1, a_src1, 16);
    __pipeline_memcpy_async(b_dst0, b_src0, 16);
    __pipeline_memcpy_async(b_dst1, b_src1, 16);
    __pipeline_commit();

    for (int kt = 0; kt < 12; kt++) {
        if (kt < 11) {
            int nb = (kt + 1) & 1;
            int koff = (kt + 1) * 32;
            __pipeline_memcpy_async(a_dst0 + nb * 18944, a_src0 + koff, 16);
            __pipeline_memcpy_async(a_dst1 + nb * 18944, a_src1 + koff, 16);
            __pipeline_memcpy_async(b_dst0 + nb * 18944, b_src0 + (size_t)koff * HW_, 16);
            __pipeline_memcpy_async(b_dst1 + nb * 18944, b_src1 + (size_t)koff * HW_, 16);
            __pipeline_commit();
            __pipeline_wait_prior(1);
        } else {
            __pipeline_wait_prior(0);
        }
        __syncthreads();

        const __nv_bfloat16* As = (const __nv_bfloat16*)(sbuf + (kt & 1) * 18944);
        const __nv_bfloat16* Bs = (const __nv_bfloat16*)(sbuf + (kt & 1) * 18944 + 10240);

        for (int ks = 0; ks < 2; ks++) {
            wx::fragment<wx::matrix_a, 16, 16, 16, __nv_bfloat16, wx::row_major> a[4];
            wx::fragment<wx::matrix_b, 16, 16, 16, __nv_bfloat16, wx::row_major> bf[2];
            for (int i = 0; i < 4; i++)
                wx::load_matrix_sync(a[i], As + (wm * 64 + i * 16) * 40 + ks * 16, 40);
            for (int j = 0; j < 2; j++)
                wx::load_matrix_sync(bf[j], Bs + (ks * 16) * 136 + wn * 32 + j * 16, 136);
            for (int i = 0; i < 4; i++)
                for (int j = 0; j < 2; j++)
                    wx::mma_sync(c[i][j], a[i], bf[j], c[i][j]);
        }
        __syncthreads();
    }

    float* Cs = (float*)sbuf;
    float* Csw = Cs + wid * 512;

    for (int i = 0; i < 4; i++) {
        wx::store_matrix_sync(Csw, c[i][0], 32, wx::mem_row_major);
        wx::store_matrix_sync(Csw + 16, c[i][1], 32, wx::mem_row_major);
        __syncwarp();
        int r = lane >> 1;
        int cb = (lane & 1) * 16;
        int gr = row0 + wm * 64 + i * 16 + r;
        int gc = col0 + wn * 32 + cb;
        float bi = bias[gr];
        for (int q = 0; q < 16; q += 4) {
            float4 v;
            v.x = Csw[r * 32 + cb + q] + bi;
            v.y = Csw[r * 32 + cb + q + 1] + bi;
            v.z = Csw[r * 32 + cb + q + 2] + bi;
            v.w = Csw[r * 32 + cb + q + 3] + bi;
            if (ob16) {
                __nv_bfloat162* op16 = (__nv_bfloat162*)(ob16 + (size_t)gr * HW_ + gc);
                op16[(q >> 1)] = __floats2bfloat162_rn(v.x, v.y);
                op16[(q >> 1) + 1] = __floats2bfloat162_rn(v.z, v.w);
            } else {
                if (rbase) {
                    const float* rp = rbase + (size_t)gr * HW_ + gc + q;
                    float4 xv = *(const float4*)(rp);
                    v.x += xv.x;
                    v.y += xv.y;
                    v.z += xv.z;
                    v.w += xv.w;
                }
                *(float4*)(ob + (size_t)gr * HW_ + gc + q) = v;
            }
        }
        __syncwarp();
    }
}

__global__ __launch_bounds__(256) void k1_gemm(const float* __restrict__ b_qkv)
{
    const int b = blockIdx.z;
    const float* nores = 0;
    float* noout = 0;
    gemm_body(g_wqb, g_xb + (size_t)b * DIM * HW_, b_qkv, nores, noout,
              g_tmpb + (size_t)b * QKV_CH * HW_);
}

__global__ __launch_bounds__(256) void k5_gemm(
    const float* __restrict__ b_proj, const float* __restrict__ x,
    float* __restrict__ out)
{
    const int b = blockIdx.z;
    __nv_bfloat16* no16 = 0;
    gemm_body(g_weffb + (size_t)b * DIM * DIM, g_vb + (size_t)b * DIM * HW_,
              b_proj, x + (size_t)b * DIM * HW_, out + (size_t)b * DIM * HW_, no16);
}

__device__ __forceinline__ float warp_red(float v)
{
    v += __shfl_down_sync(0xffffffffu, v, 16);
    v += __shfl_down_sync(0xffffffffu, v, 8);
    v += __shfl_down_sync(0xffffffffu, v, 4);
    v += __shfl_down_sync(0xffffffffu, v, 2);
    v += __shfl_down_sync(0xffffffffu, v, 1);
    return v;
}

// Fused dwconv(q,k) + Gram/norm partial reductions.
__global__ __launch_bounds__(256) void k2qk(
    const float* __restrict__ w_dw, const float* __restrict__ b_dw)
{
    const int b = blockIdx.z;
    const int cc = blockIdx.y;
    const int strip = blockIdx.x;
    const int y0 = strip * 8;

    __shared__ __align__(16) char sbuf[46080];
    __shared__ float sw[16][9];
    __shared__ float sbias[16];

    __nv_bfloat16* sm = (__nv_bfloat16*)sbuf;
    const __nv_bfloat16* tb = g_tmpb + (size_t)b * QKV_CH * HW_;

    for (int idx = threadIdx.x; idx < 2560; idx += 256) {
        int ch = idx / 160;
        int rem = idx - ch * 160;
        int row = rem >> 4;
        int u = rem & 15;
        int gy = y0 - 1 + row;
        uint4 v;
        v.x = 0u; v.y = 0u; v.z = 0u; v.w = 0u;
        if (gy >= 0 && gy < 128) {
            int chg = ch * 48 + cc;
            if (ch >= 8) chg = 384 + (ch - 8) * 48 + cc;
            v = *(const uint4*)(tb + (size_t)chg * HW_ + gy * 128 + u * 8);
        }
        *(uint4*)(sm + ((ch * 10 + row) * 144 + 8 + u * 8)) = v;
    }
    for (int idx = threadIdx.x; idx < 320; idx += 256) {
        int ch = idx / 20;
        int rem = idx - ch * 20;
        int row = rem >> 1;
        int col = 7;
        if (rem & 1) col = 136;
        sm[(ch * 10 + row) * 144 + col] = __float2bfloat16(0.f);
    }
    if (threadIdx.x < 144) {
        int ci = threadIdx.x / 9;
        int j = threadIdx.x - ci * 9;
        int chg = ci * 48 + cc;
        if (ci >= 8) chg = 384 + (ci - 8) * 48 + cc;
        sw[ci][j] = w_dw[chg * 9 + j];
    }
    if (threadIdx.x >= 144 && threadIdx.x < 160) {
        int ci = threadIdx.x - 144;
        int chg = ci * 48 + cc;
        if (ci >= 8) chg = 384 + (ci - 8) * 48 + cc;
        sbias[ci] = b_dw[chg];
    }
    __syncthreads();

    const int r = threadIdx.x >> 5;
    const int x0 = (threadIdx.x & 31) * 4;

    float acc[8][8];
    float aq[8];
    float ak[8];
    float qo[8][4];
    #pragma unroll
    for (int n = 0; n < 8; n++) {
        aq[n] = 0.f;
        ak[n] = 0.f;
        #pragma unroll
        for (int m = 0; m < 8; m++) acc[n][m] = 0.f;
    }

    #pragma unroll
    for (int n = 0; n < 8; n++) {
        float v0[8];
        float v1[8];
        float v2[8];
        #pragma unroll
        for (int j = 0; j < 4; j++) {
            int base0 = (n * 10 + r) * 144 + 6 + x0 + 2 * j;
            float2 f0 = __bfloat1622float2(*(const __nv_bfloat162*)(sm + base0));
            float2 f1 = __bfloat1622float2(*(const __nv_bfloat162*)(sm + base0 + 144));
            float2 f2 = __bfloat1622float2(*(const __nv_bfloat162*)(sm + base0 + 288));
            v0[2 * j] = f0.x; v0[2 * j + 1] = f0.y;
            v1[2 * j] = f1.x; v1[2 * j + 1] = f1.y;
            v2[2 * j] = f2.x; v2[2 * j + 1] = f2.y;
        }
        float bi = sbias[n];
        #pragma unroll
        for (int i = 0; i < 4; i++) {
            float o = bi;
            o += sw[n][0] * v0[1 + i];
            o += sw[n][1] * v0[2 + i];
            o += sw[n][2] * v0[3 + i];
            o += sw[n][3] * v1[1 + i];
            o += sw[n][4] * v1[2 + i];
            o += sw[n][5] * v1[3 + i];
            o += sw[n][6] * v2[1 + i];
            o += sw[n][7] * v2[2 + i];
            o += sw[n][8] * v2[3 + i];
            qo[n][i] = o;
            aq[n] += o * o;
        }
    }

    #pragma unroll
    for (int m = 0; m < 8; m++) {
        float v0[8];
        float v1[8];
        float v2[8];
        #pragma unroll
        for (int j = 0; j < 4; j++) {
            int base0 = ((8 + m) * 10 + r) * 144 + 6 + x0 + 2 * j;
            float2 f0 = __bfloat1622float2(*(const __nv_bfloat162*)(sm + base0));
            float2 f1 = __bfloat1622float2(*(const __nv_bfloat162*)(sm + base0 + 144));
            float2 f2 = __bfloat1622float2(*(const __nv_bfloat162*)(sm + base0 + 288));
            v0[2 * j] = f0.x; v0[2 * j + 1] = f0.y;
            v1[2 * j] = f1.x; v1[2 * j + 1] = f1.y;
            v2[2 * j] = f2.x; v2[2 * j + 1] = f2.y;
        }
        float bi = sbias[8 + m];
        float ko[4];
        #pragma unroll
        for (int i = 0; i < 4; i++) {
            float o = bi;
            o += sw[8 + m][0] * v0[1 + i];
            o += sw[8 + m][1] * v0[2 + i];
            o += sw[8 + m][2] * v0[3 + i];
            o += sw[8 + m][3] * v1[1 + i];
            o += sw[8 + m][4] * v1[2 + i];
            o += sw[8 + m][5] * v1[3 + i];
            o += sw[8 + m][6] * v2[1 + i];
            o += sw[8 + m][7] * v2[2 + i];
            o += sw[8 + m][8] * v2[3 + i];
            ko[i] = o;
            ak[m] += o * o;
        }
        #pragma unroll
        for (int n = 0; n < 8; n++) {
            #pragma unroll
            for (int i = 0; i < 4; i++) acc[n][m] += qo[n][i] * ko[i];
        }
    }

    __syncthreads();
    float* red = (float*)sbuf;
    const int lane = threadIdx.x & 31;
    const int wid = threadIdx.x >> 5;
    #pragma unroll
    for (int n = 0; n < 8; n++) {
        #pragma unroll
        for (int m = 0; m < 8; m++) {
            float s = warp_red(acc[n][m]);
            if (lane == 0) red[wid * 80 + n * 8 + m] = s;
        }
        float s1 = warp_red(aq[n]);
        if (lane == 0) red[wid * 80 + 64 + n] = s1;
        float s2 = warp_red(ak[n]);
        if (lane == 0) red[wid * 80 + 72 + n] = s2;
    }
    __syncthreads();
    if (threadIdx.x < 80) {
        float t = 0.f;
        #pragma unroll
        for (int w = 0; w < 8; w++) t += red[w * 80 + threadIdx.x];
        g_part[((size_t)b * NPART + cc * 16 + strip) * 80 + threadIdx.x] = t;
    }
}

// dwconv for v channels only -> g_vb (bf16)
__global__ __launch_bounds__(256) void k2v(
    const float* __restrict__ w_dw, const float* __restrict__ b_dw)
{
    const int chv = blockIdx.y;
    const int ch = 768 + chv;
    const int b = blockIdx.z;
    const int y0 = blockIdx.x * 16;

    __shared__ __align__(16) __nv_bfloat16 smv[18 * 144];
    const __nv_bfloat16* src = g_tmpb + ((size_t)b * QKV_CH + ch) * HW_;

    for (int idx = threadIdx.x; idx < 288; idx += 256) {
        int row = idx >> 4;
        int u = idx & 15;
        int gy = y0 - 1 + row;
        uint4 v;
        v.x = 0u; v.y = 0u; v.z = 0u; v.w = 0u;
        if (gy >= 0 && gy < 128) v = *(const uint4*)(src + gy * 128 + u * 8);
        *(uint4*)(smv + (row * 144 + 8 + u * 8)) = v;
    }
    if (threadIdx.x < 36) {
        int row = threadIdx.x >> 1;
        int col = 7;
        if (threadIdx.x & 1) col = 136;
        smv[row * 144 + col] = __float2bfloat16(0.f);
    }
    __syncthreads();

    float wv[9];
    #pragma unroll
    for (int i = 0; i < 9; i++) wv[i] = w_dw[ch * 9 + i];
    float bi = b_dw[ch];

    const int r = threadIdx.x >> 4;
    const int x0 = (threadIdx.x & 15) * 8;

    float v0[12];
    float v1[12];
    float v2[12];
    #pragma unroll
    for (int j = 0; j < 6; j++) {
        int base0 = r * 144 + 6 + x0 + 2 * j;
        float2 f0 = __bfloat1622float2(*(const __nv_bfloat162*)(smv + base0));
        float2 f1 = __bfloat1622float2(*(const __nv_bfloat162*)(smv + base0 + 144));
        float2 f2 = __bfloat1622float2(*(const __nv_bfloat162*)(smv + base0 + 288));
        v0[2 * j] = f0.x; v0[2 * j + 1] = f0.y;
        v1[2 * j] = f1.x; v1[2 * j + 1] = f1.y;
        v2[2 * j] = f2.x; v2[2 * j + 1] = f2.y;
    }

    float o[8];
    #pragma unroll
    for (int i = 0; i < 8; i++) {
        float t = bi;
        t += wv[0] * v0[1 + i];
        t += wv[1] * v0[2 + i];
        t += wv[2] * v0[3 + i];
        t += wv[3] * v1[1 + i];
        t += wv[4] * v1[2 + i];
        t += wv[5] * v1[3 + i];
        t += wv[6] * v2[1 + i];
        t += wv[7] * v2[2 + i];
        t += wv[8] * v2[3 + i];
        o[i] = t;
    }

    const int p = (y0 + r) * 128 + x0;
    __nv_bfloat162* dst = (__nv_bfloat162*)(g_vb + ((size_t)b * DIM + chv) * HW_ + p);
    dst[0] = __floats2bfloat162_rn(o[0], o[1]);
    dst[1] = __floats2bfloat162_rn(o[2], o[3]);
    dst[2] = __floats2bfloat162_rn(o[4], o[5]);
    dst[3] = __floats2bfloat162_rn(o[6], o[7]);
}

__global__ __launch_bounds__(640) void k4a_softmax(const float* __restrict__ temperature)
{
    const int b = blockIdx.x;
    __shared__ float red[80];

    const int e = threadIdx.x >> 3;
    const int j = threadIdx.x & 7;
    float t = 0.f;
    for (int s = j; s < NPART; s += 8)
        t += g_part[((size_t)b * NPART + s) * 80 + e];
    t += __shfl_down_sync(0xffffffffu, t, 4);
    t += __shfl_down_sync(0xffffffffu, t, 2);
    t += __shfl_down_sync(0xffffffffu, t, 1);
    if (j == 0) red[e] = t;
    __syncthreads();

    if (threadIdx.x < 8) {
        const int n = threadIdx.x;
        const float temp = temperature[0];
        float qn = fmaxf(sqrtf(red[64 + n]), 1e-12f);
        float logit[8];
        float mx = -1e30f;
        #pragma unroll
        for (int m = 0; m < 8; m++) {
            float kn = fmaxf(sqrtf(red[72 + m]), 1e-12f);
            float l = temp * red[n * 8 + m] / (qn * kn);
            logit[m] = l;
            mx = fmaxf(mx, l);
        }
        float sum = 0.f;
        float ex[8];
        #pragma unroll
        for (int m = 0; m < 8; m++) {
            ex[m] = expf(logit[m] - mx);
            sum += ex[m];
        }
        float inv = 1.f / sum;
        #pragma unroll
        for (int m = 0; m < 8; m++) g_attn[b * 64 + n * 8 + m] = ex[m] * inv;
    }
}

__global__ __launch_bounds__(256) void k4b_weff(const float* __restrict__ w_proj)
{
    const int b = blockIdx.y;
    __shared__ float at[64];
    if (threadIdx.x < 64) at[threadIdx.x] = g_attn[b * 64 + threadIdx.x];
    __syncthreads();

    const int idx = blockIdx.x * 256 + threadIdx.x;
    const int co = idx / DIM;
    const int jj = idx % DIM;
    const int m = jj / CC_;
    const int cc = jj % CC_;
    float s = 0.f;
    #pragma unroll
    for (int n = 0; n < 8; n++)
        s += at[n * 8 + m] * __ldg(&w_proj[co * DIM + n * CC_ + cc]);
    g_weffb[(size_t)b * DIM * DIM + idx] = __float2bfloat16(s);
}

extern "C" void kernel_launch(void* const* d_in, const int* in_sizes, int n_in,
                              void* d_out, int out_size)
{
    const float* x = (const float*)d_in[0];
    const float* temp = (const float*)d_in[1];
    const float* w_qkv = (const float*)d_in[2];
    const float* b_qkv = (const float*)d_in[3];
    const float* w_dw = (const float*)d_in[4];
    const float* b_dw = (const float*)d_in[5];
    const float* w_proj = (const float*)d_in[6];
    const float* b_proj = (const float*)d_in[7];
    float* out = (float*)d_out;

    int gcx = 24576;
    int gcw = 432;
    dim3 g1(128, 9, 4);
    dim3 gqk(16, 48, 4);
    dim3 gv(8, 384, 4);
    dim3 g4b(576, 4);
    dim3 g5(128, 3, 4);
    int nb4 = 4;

    kc_conv_x<<<gcx, 256>>>(x);
    kc_conv_w<<<gcw, 256>>>(w_qkv);
    k1_gemm<<<g1, 256>>>(b_qkv);
    k2qk<<<gqk, 256>>>(w_dw, b_dw);
    k2v<<<gv, 256>>>(w_dw, b_dw);
    k4a_softmax<<<nb4, 640>>>(temp);
    k4b_weff<<<g4b, 256>>>(w_proj);
    k5_gemm<<<g5, 256>>>(b_proj, x, out);
}